// round 4
// baseline (speedup 1.0000x reference)
#include <cuda_runtime.h>

typedef unsigned long long u64;

#define LEAKY_SLOPE 0.01f
#define NTHREADS 256

// ---- packed f32x2 helpers (Blackwell dual-FP32 pipe; ptxas only emits FFMA2
// ---- from explicit PTX fma.rn.f32x2) ----
__device__ __forceinline__ u64 pack2(float a, float b) {
    u64 r; asm("mov.b64 %0, {%1, %2};" : "=l"(r) : "f"(a), "f"(b)); return r;
}
__device__ __forceinline__ void unpack2(u64 v, float& a, float& b) {
    asm("mov.b64 {%0, %1}, %2;" : "=f"(a), "=f"(b) : "l"(v));
}
__device__ __forceinline__ u64 ffma2(u64 a, u64 b, u64 c) {
    u64 d; asm("fma.rn.f32x2 %0, %1, %2, %3;" : "=l"(d) : "l"(a), "l"(b), "l"(c));
    return d;
}
__device__ __forceinline__ float hadd2(u64 v) {
    float a, b; unpack2(v, a, b); return a + b;
}
__device__ __forceinline__ float leaky(float x) {
    // slope in (0,1): leaky(x) == max(x, slope*x)
    return fmaxf(x, LEAKY_SLOPE * x);
}

// Bilinear interpolation of a 256x256x3 grid at (u,v) in [0,1).
__device__ __forceinline__ void interp3(const float* __restrict__ g,
                                        float u, float v, float* o) {
    float fx = u * 255.0f;
    float fy = v * 255.0f;
    int x0 = (int)fx;
    int y0 = (int)fy;
    float xf = fx - (float)x0;
    float yf = fy - (float)y0;
    int x1 = min(x0 + 1, 255);
    int y1 = min(y0 + 1, 255);
    const float* tl = g + (y0 * 256 + x0) * 3;
    const float* tr = g + (y0 * 256 + x1) * 3;
    const float* bl = g + (y1 * 256 + x0) * 3;
    const float* br = g + (y1 * 256 + x1) * 3;
    float omx = 1.0f - xf;
    float omy = 1.0f - yf;
#pragma unroll
    for (int c = 0; c < 3; c++) {
        float top = omx * __ldg(tl + c) + xf * __ldg(tr + c);
        float bot = omx * __ldg(bl + c) + xf * __ldg(br + c);
        o[c] = omy * top + yf * bot;
    }
}

__global__ void __launch_bounds__(NTHREADS)
mlp_fused_kernel(const float* __restrict__ pos,
                 const float* __restrict__ dir,
                 const float* __restrict__ pos_grid,
                 const float* __restrict__ dir_grid,
                 const float* __restrict__ W1, const float* __restrict__ b1,
                 const float* __restrict__ W2, const float* __restrict__ b2,
                 const float* __restrict__ W3, const float* __restrict__ b3,
                 float* __restrict__ out, int n) {
    __shared__ __align__(16) float sW1[64 * 6];
    __shared__ __align__(16) float sW2[64 * 64];
    __shared__ __align__(16) float sW3[64];
    __shared__ float sB1[64];
    __shared__ float sB2[64];
    __shared__ float sB3;

    const int t = threadIdx.x;
    const int idx = blockIdx.x * NTHREADS + t;

    // Prefetch per-point inputs FIRST so the loads overlap weight staging.
    // Clamp the index: tail-block threads must not read out of bounds.
    const int cidx = min(idx, n - 1);
    float2 p = __ldg(((const float2*)pos) + cidx);
    float2 d = __ldg(((const float2*)dir) + cidx);

    // Stage all weights into shared (warp-broadcast reads later; conflict-free).
    for (int i = t; i < 64 * 6; i += NTHREADS) sW1[i] = W1[i];
    for (int i = t; i < 64 * 64; i += NTHREADS) sW2[i] = W2[i];
    if (t < 64) {
        sW3[t] = W3[t];
        sB1[t] = b1[t];
        sB2[t] = b2[t];
    }
    if (t == 0) sB3 = b3[0];
    __syncthreads();

    if (idx >= n) return;

    // ---- grid encoding: 6 input features ----
    float x6[6];
    interp3(pos_grid, p.x, p.y, x6);
    interp3(dir_grid, d.x, d.y, x6 + 3);

    // ---- layer 1: 6 -> 64, leaky relu. Pack over k (k-pairs). ----
    u64 xp0 = pack2(x6[0], x6[1]);
    u64 xp1 = pack2(x6[2], x6[3]);
    u64 xp2 = pack2(x6[4], x6[5]);

    u64 h1[32];  // layer-1 activations packed as consecutive k-pairs
#pragma unroll
    for (int tt = 0; tt < 32; tt++) {
        const int ja = 2 * tt, jb = 2 * tt + 1;
        const u64* ra = (const u64*)(sW1 + ja * 6);  // 24B rows: 8B-aligned
        const u64* rb = (const u64*)(sW1 + jb * 6);
        u64 aa = ffma2(xp0, ra[0],
                 ffma2(xp1, ra[1],
                 ffma2(xp2, ra[2], 0ull)));
        u64 ab = ffma2(xp0, rb[0],
                 ffma2(xp1, rb[1],
                 ffma2(xp2, rb[2], 0ull)));
        float va = leaky(hadd2(aa) + sB1[ja]);
        float vb = leaky(hadd2(ab) + sB1[jb]);
        h1[tt] = pack2(va, vb);
    }

    // ---- layer 2 (dominant) with layer 3 fused into the epilogue. ----
    // Two output rows per iteration = 2 independent FFMA2 chains (lat 4 /
    // rt 2). Each (va, vb) pair is immediately folded into the logit
    // accumulator, so no h2[] array exists and peak live registers stay
    // ~h1 + accumulators.
    const u64* w3p = (const u64*)sW3;
    u64 logit_acc = 0ull;
#pragma unroll
    for (int tt = 0; tt < 32; tt++) {
        const ulonglong2* ra = (const ulonglong2*)(sW2 + (2 * tt) * 64);
        const ulonglong2* rb = (const ulonglong2*)(sW2 + (2 * tt + 1) * 64);
        u64 aa = 0ull, ab = 0ull;
#pragma unroll
        for (int i = 0; i < 16; i++) {
            ulonglong2 wa = ra[i];
            ulonglong2 wb = rb[i];
            aa = ffma2(h1[2 * i + 0], wa.x, aa);
            ab = ffma2(h1[2 * i + 0], wb.x, ab);
            aa = ffma2(h1[2 * i + 1], wa.y, aa);
            ab = ffma2(h1[2 * i + 1], wb.y, ab);
        }
        float va = leaky(hadd2(aa) + sB2[2 * tt]);
        float vb = leaky(hadd2(ab) + sB2[2 * tt + 1]);
        logit_acc = ffma2(pack2(va, vb), w3p[tt], logit_acc);
    }

    // ---- layer 3 epilogue: sigmoid ----
    // __expf: one MUFU.EX2 (+scale); __fdividef(1,x): one MUFU.RCP.
    // Combined error ~2-3 ulp on a (0,1) output — far inside the 1e-3 gate.
    float logit = hadd2(logit_acc) + sB3;
    out[idx] = __fdividef(1.0f, 1.0f + __expf(-logit));
}

extern "C" void kernel_launch(void* const* d_in, const int* in_sizes, int n_in,
                              void* d_out, int out_size) {
    const float* pos = (const float*)d_in[0];
    const float* dir = (const float*)d_in[1];
    const float* pos_grid = (const float*)d_in[2];
    const float* dir_grid = (const float*)d_in[3];
    const float* W1 = (const float*)d_in[4];
    const float* b1 = (const float*)d_in[5];
    const float* W2 = (const float*)d_in[6];
    const float* b2 = (const float*)d_in[7];
    const float* W3 = (const float*)d_in[8];
    const float* b3 = (const float*)d_in[9];
    float* out = (float*)d_out;

    const int n = in_sizes[0] / 2;
    const int blocks = (n + NTHREADS - 1) / NTHREADS;
    mlp_fused_kernel<<<blocks, NTHREADS>>>(pos, dir, pos_grid, dir_grid,
                                           W1, b1, W2, b2, W3, b3, out, n);
}

// round 11
// speedup vs baseline: 1.2103x; 1.2103x over previous
#include <cuda_runtime.h>

typedef unsigned long long u64;

#define LEAKY_SLOPE 0.01f
#define NTHREADS 128   // 2 points per thread -> 256 points per block

// ---- packed f32x2 helpers (Blackwell dual-FP32 pipe; ptxas only emits FFMA2
// ---- from explicit PTX fma.rn.f32x2) ----
__device__ __forceinline__ u64 pack2(float a, float b) {
    u64 r; asm("mov.b64 %0, {%1, %2};" : "=l"(r) : "f"(a), "f"(b)); return r;
}
__device__ __forceinline__ void unpack2(u64 v, float& a, float& b) {
    asm("mov.b64 {%0, %1}, %2;" : "=f"(a), "=f"(b) : "l"(v));
}
__device__ __forceinline__ u64 ffma2(u64 a, u64 b, u64 c) {
    u64 d; asm("fma.rn.f32x2 %0, %1, %2, %3;" : "=l"(d) : "l"(a), "l"(b), "l"(c));
    return d;
}
__device__ __forceinline__ float hadd2(u64 v) {
    float a, b; unpack2(v, a, b); return a + b;
}
__device__ __forceinline__ float leaky(float x) {
    return fmaxf(x, LEAKY_SLOPE * x);  // slope in (0,1)
}
__device__ __forceinline__ float sigmoidf_fast(float x) {
    // MUFU.EX2 (+scale) + MUFU.RCP; ~2-3 ulp on (0,1) output, gate is 1e-3.
    return __fdividef(1.0f, 1.0f + __expf(-x));
}

// Bilinear interpolation of a 256x256x3 grid at (u,v) in [0,1).
__device__ __forceinline__ void interp3(const float* __restrict__ g,
                                        float u, float v, float* o) {
    float fx = u * 255.0f;
    float fy = v * 255.0f;
    int x0 = (int)fx;
    int y0 = (int)fy;
    float xf = fx - (float)x0;
    float yf = fy - (float)y0;
    int x1 = min(x0 + 1, 255);
    int y1 = min(y0 + 1, 255);
    const float* tl = g + (y0 * 256 + x0) * 3;
    const float* tr = g + (y0 * 256 + x1) * 3;
    const float* bl = g + (y1 * 256 + x0) * 3;
    const float* br = g + (y1 * 256 + x1) * 3;
    float omx = 1.0f - xf;
    float omy = 1.0f - yf;
#pragma unroll
    for (int c = 0; c < 3; c++) {
        float top = omx * __ldg(tl + c) + xf * __ldg(tr + c);
        float bot = omx * __ldg(bl + c) + xf * __ldg(br + c);
        o[c] = omy * top + yf * bot;
    }
}

__global__ void __launch_bounds__(NTHREADS)
mlp_fused_kernel(const float* __restrict__ pos,
                 const float* __restrict__ dir,
                 const float* __restrict__ pos_grid,
                 const float* __restrict__ dir_grid,
                 const float* __restrict__ W1, const float* __restrict__ b1,
                 const float* __restrict__ W2, const float* __restrict__ b2,
                 const float* __restrict__ W3, const float* __restrict__ b3,
                 float* __restrict__ out, int n) {
    __shared__ __align__(16) float sW1[64 * 6];
    __shared__ __align__(16) float sW2[64 * 64];
    __shared__ __align__(16) float sW3[64];
    __shared__ float sB1[64];
    __shared__ float sB2[64];
    __shared__ float sB3;

    const int t = threadIdx.x;
    const int pi = blockIdx.x * NTHREADS + t;  // pair index
    const int i0 = 2 * pi;                     // first point of the pair
    const bool v0 = (i0 < n);
    const bool v1 = (i0 + 1 < n);

    // Prefetch both points' inputs (coalesced float4 = 2 points) before
    // staging weights, so the global loads overlap the staging.
    float4 p, d;
    if (v1) {  // both points valid: one 16B load each
        p = __ldg(((const float4*)pos) + pi);
        d = __ldg(((const float4*)dir) + pi);
    } else {   // tail: clamp to last valid point, load 8B
        int c = min(i0, n - 1);
        float2 pp = __ldg(((const float2*)pos) + c);
        float2 dd = __ldg(((const float2*)dir) + c);
        p = make_float4(pp.x, pp.y, pp.x, pp.y);
        d = make_float4(dd.x, dd.y, dd.x, dd.y);
    }

    // Stage all weights into shared.
    for (int i = t; i < 64 * 6; i += NTHREADS) sW1[i] = W1[i];
    for (int i = t; i < 64 * 64; i += NTHREADS) sW2[i] = W2[i];
    if (t < 64) {
        sW3[t] = W3[t];
        sB1[t] = b1[t];
        sB2[t] = b2[t];
    }
    if (t == 0) sB3 = b3[0];
    __syncthreads();

    if (!v0) return;

    // ---- grid encoding for both points ----
    float xa[6], xb[6];
    interp3(pos_grid, p.x, p.y, xa);
    interp3(dir_grid, d.x, d.y, xa + 3);
    interp3(pos_grid, p.z, p.w, xb);
    interp3(dir_grid, d.z, d.w, xb + 3);

    u64 xa0 = pack2(xa[0], xa[1]), xa1 = pack2(xa[2], xa[3]), xa2 = pack2(xa[4], xa[5]);
    u64 xb0 = pack2(xb[0], xb[1]), xb1 = pack2(xb[2], xb[3]), xb2 = pack2(xb[4], xb[5]);

    // ---- layer 1: 6 -> 64 for both points; weights loaded ONCE per row pair ----
    u64 h1a[32], h1b[32];  // activations as packed k-pairs, per point
#pragma unroll
    for (int tt = 0; tt < 32; tt++) {
        const int ja = 2 * tt, jb = 2 * tt + 1;
        const u64* ra = (const u64*)(sW1 + ja * 6);
        const u64* rb = (const u64*)(sW1 + jb * 6);
        u64 r0 = ra[0], r1 = ra[1], r2 = ra[2];
        u64 s0 = rb[0], s1 = rb[1], s2 = rb[2];
        u64 aA = ffma2(xa0, r0, ffma2(xa1, r1, ffma2(xa2, r2, 0ull)));
        u64 aB = ffma2(xa0, s0, ffma2(xa1, s1, ffma2(xa2, s2, 0ull)));
        u64 bA = ffma2(xb0, r0, ffma2(xb1, r1, ffma2(xb2, r2, 0ull)));
        u64 bB = ffma2(xb0, s0, ffma2(xb1, s1, ffma2(xb2, s2, 0ull)));
        float bja = sB1[ja], bjb = sB1[jb];
        h1a[tt] = pack2(leaky(hadd2(aA) + bja), leaky(hadd2(aB) + bjb));
        h1b[tt] = pack2(leaky(hadd2(bA) + bja), leaky(hadd2(bB) + bjb));
    }

    // ---- layer 2 (dominant), layer 3 fused into the epilogue. ----
    // Each W2 row pair is loaded ONCE (2x broadcast LDS.128 per inner step)
    // and applied to BOTH points -> 8 FFMA2 per 32B of shared traffic. This
    // halves the L1 return-wavefront load per point (the R4 binder at 96%)
    // and makes the fma pipe the binding resource. Four independent FFMA2
    // chains cover lat4/rt2 from within one warp.
    const u64* w3p = (const u64*)sW3;
    u64 logit_a = 0ull, logit_b = 0ull;
#pragma unroll
    for (int tt = 0; tt < 32; tt++) {
        const ulonglong2* ra = (const ulonglong2*)(sW2 + (2 * tt) * 64);
        const ulonglong2* rb = (const ulonglong2*)(sW2 + (2 * tt + 1) * 64);
        u64 aA = 0ull, aB = 0ull, bA = 0ull, bB = 0ull;
#pragma unroll
        for (int i = 0; i < 16; i++) {
            ulonglong2 wa = ra[i];
            ulonglong2 wb = rb[i];
            u64 ha0 = h1a[2 * i + 0], ha1 = h1a[2 * i + 1];
            u64 hb0 = h1b[2 * i + 0], hb1 = h1b[2 * i + 1];
            aA = ffma2(ha0, wa.x, aA);
            aB = ffma2(ha0, wb.x, aB);
            bA = ffma2(hb0, wa.x, bA);
            bB = ffma2(hb0, wb.x, bB);
            aA = ffma2(ha1, wa.y, aA);
            aB = ffma2(ha1, wb.y, aB);
            bA = ffma2(hb1, wa.y, bA);
            bB = ffma2(hb1, wb.y, bB);
        }
        float b2a = sB2[2 * tt], b2b = sB2[2 * tt + 1];
        u64 w3v = w3p[tt];
        u64 h2a = pack2(leaky(hadd2(aA) + b2a), leaky(hadd2(aB) + b2b));
        u64 h2b = pack2(leaky(hadd2(bA) + b2a), leaky(hadd2(bB) + b2b));
        logit_a = ffma2(h2a, w3v, logit_a);
        logit_b = ffma2(h2b, w3v, logit_b);
    }

    // ---- sigmoid epilogue; paired 8B store when both points valid ----
    float oa = sigmoidf_fast(hadd2(logit_a) + sB3);
    if (v1) {
        float ob = sigmoidf_fast(hadd2(logit_b) + sB3);
        ((float2*)out)[pi] = make_float2(oa, ob);   // one STG.64, coalesced
    } else {
        out[i0] = oa;
    }
}

extern "C" void kernel_launch(void* const* d_in, const int* in_sizes, int n_in,
                              void* d_out, int out_size) {
    const float* pos = (const float*)d_in[0];
    const float* dir = (const float*)d_in[1];
    const float* pos_grid = (const float*)d_in[2];
    const float* dir_grid = (const float*)d_in[3];
    const float* W1 = (const float*)d_in[4];
    const float* b1 = (const float*)d_in[5];
    const float* W2 = (const float*)d_in[6];
    const float* b2 = (const float*)d_in[7];
    const float* W3 = (const float*)d_in[8];
    const float* b3 = (const float*)d_in[9];
    float* out = (float*)d_out;

    const int n = in_sizes[0] / 2;               // number of points
    const int pairs = (n + 1) / 2;               // 2 points per thread
    const int blocks = (pairs + NTHREADS - 1) / NTHREADS;
    mlp_fused_kernel<<<blocks, NTHREADS>>>(pos, dir, pos_grid, dir_grid,
                                           W1, b1, W2, b2, W3, b3, out, n);
}